// round 1
// baseline (speedup 1.0000x reference)
#include <cuda_runtime.h>
#include <math.h>

// Problem constants
#define B_  32
#define L_  512
#define H_  8
#define E_  64
#define S_  512

// Tiling
#define BL  32          // query rows per CTA
#define SC  256         // key/value chunk rows held in smem
#define NCH 2           // S / SC
#define NT  256         // threads per CTA

// Padded smem strides (floats)
#define KST 66          // K/V tile row stride: stride%32==2 -> conflict-free LDS.64
#define SST 514         // series row stride: even (float2) and %32==2

#define SMEM_FLOATS (BL*E_ + SC*KST + BL*SST)
#define SMEM_BYTES  (SMEM_FLOATS * 4)

// Output layout: [ V (B,L,H,E) | series (B,H,L,S) | prior (B,H,L,S) ]
#define OFF_SER ((size_t)8388608)
#define OFF_PRI ((size_t)75497472)

// Packed f32x2 FMA (Blackwell): 2 fp32 FMAs per fma-pipe issue slot.
// ptxas will not auto-fuse this from C++; must come from PTX.
static __device__ __forceinline__ float2 ffma2(float2 a, float2 b, float2 c) {
    float2 d;
    asm("{\n\t"
        ".reg .b64 ra, rb, rc, rd;\n\t"
        "mov.b64 ra, {%2,%3};\n\t"
        "mov.b64 rb, {%4,%5};\n\t"
        "mov.b64 rc, {%6,%7};\n\t"
        "fma.rn.f32x2 rd, ra, rb, rc;\n\t"
        "mov.b64 {%0,%1}, rd;\n\t"
        "}"
        : "=f"(d.x), "=f"(d.y)
        : "f"(a.x), "f"(a.y), "f"(b.x), "f"(b.y), "f"(c.x), "f"(c.y));
    return d;
}

__global__ void __launch_bounds__(NT, 1)
anomaly_attn_kernel(const float* __restrict__ q,
                    const float* __restrict__ kg,
                    const float* __restrict__ vg,
                    const float* __restrict__ sg,
                    float* __restrict__ out)
{
    extern __shared__ float sm[];
    float* sQ   = sm;                 // [BL][E_]
    float* sKV  = sm + BL*E_;         // [SC][KST]
    float* sSer = sKV + SC*KST;       // [BL][SST]

    const int tid  = threadIdx.x;
    const int lane = tid & 31;
    const int wid  = tid >> 5;        // 0..7
    const int tile = blockIdx.x;      // 0..15
    const int h    = blockIdx.y;
    const int b    = blockIdx.z;
    const int l0   = tile * BL;

    const float* qb = q  + (((size_t)b*L_ + l0)*H_ + h)*E_;   // row stride H_*E_
    const float* kb = kg + ((size_t)b*L_*H_ + h)*E_;          // key row s: + s*H_*E_
    const float* vb = vg + ((size_t)b*L_*H_ + h)*E_;

    // ---- Load Q tile (32x64) ----
    #pragma unroll 4
    for (int t = tid; t < BL*32; t += NT) {
        int r = t >> 5, c2 = t & 31;
        *(float2*)&sQ[r*E_ + c2*2] =
            *(const float2*)&qb[(size_t)r*(H_*E_) + c2*2];
    }

    const float scale = 0.125f;   // 1/sqrt(64)
    float rs[4] = {0.f, 0.f, 0.f, 0.f};   // row sums of exp(logits)

    // ---- QK^T + exp, chunked over S ----
    for (int ch = 0; ch < NCH; ++ch) {
        __syncthreads();
        #pragma unroll 8
        for (int t = tid; t < SC*32; t += NT) {
            int r = t >> 5, c2 = t & 31;
            *(float2*)&sKV[r*KST + c2*2] =
                *(const float2*)&kb[(size_t)(ch*SC + r)*(H_*E_) + c2*2];
        }
        __syncthreads();

        float2 acc[4][8];
        #pragma unroll
        for (int i = 0; i < 4; ++i)
            #pragma unroll
            for (int j = 0; j < 8; ++j)
                acc[i][j] = make_float2(0.f, 0.f);

        #pragma unroll 4
        for (int e2 = 0; e2 < 32; ++e2) {
            float2 a[4], bb[8];
            #pragma unroll
            for (int i = 0; i < 4; ++i)       // broadcast loads
                a[i] = *(float2*)&sQ[(wid*4 + i)*E_ + e2*2];
            #pragma unroll
            for (int j = 0; j < 8; ++j)       // conflict-free spread loads
                bb[j] = *(float2*)&sKV[(j*32 + lane)*KST + e2*2];
            #pragma unroll
            for (int i = 0; i < 4; ++i)
                #pragma unroll
                for (int j = 0; j < 8; ++j)
                    acc[i][j] = ffma2(a[i], bb[j], acc[i][j]);
        }

        // exp (no max-shift: |logits| <= ~8, softmax is shift-invariant)
        #pragma unroll
        for (int i = 0; i < 4; ++i) {
            int r = wid*4 + i;
            #pragma unroll
            for (int j = 0; j < 8; ++j) {
                int s = ch*SC + j*32 + lane;
                float p = __expf((acc[i][j].x + acc[i][j].y) * scale);
                sSer[r*SST + s] = p;
                rs[i] += p;
            }
        }
    }

    // ---- Row-sum reduce across the warp (each warp owns rows wid*4..wid*4+3) ----
    #pragma unroll
    for (int i = 0; i < 4; ++i) {
        float x = rs[i];
        #pragma unroll
        for (int off = 16; off > 0; off >>= 1)
            x += __shfl_xor_sync(0xffffffffu, x, off);
        rs[i] = 1.0f / x;
    }

    // ---- Gaussian prior per-row constants ----
    // Reproduce reference's fp32 cancellation in (3^sig - 1):
    // accurate expm1, then quantize through fl32(1+u)-1.
    float pc0[4], pc1[4];
    #pragma unroll
    for (int i = 0; i < 4; ++i) {
        int lg = l0 + wid*4 + i;
        float sv = sg[((size_t)b*L_ + lg)*H_ + h];
        float s1 = 1.0f / (1.0f + __expf(-5.0f * sv)) + 1e-5f;
        float u  = expm1f(s1 * 1.0986122886681098f);       // 3^s1 - 1, accurate
        float t3 = __fadd_rn(__fadd_rn(1.0f, u), -1.0f);   // mimic fl32(3^s1) - 1
        pc0[i] = 0.3989422804014327f / t3;
        pc1[i] = -0.5f / (t3 * t3);
    }

    // ---- Normalize series, write series + prior to gmem, finalize sSer ----
    #pragma unroll
    for (int i = 0; i < 4; ++i) {
        int r  = wid*4 + i;
        int lg = l0 + r;
        float* serrow = out + OFF_SER + (((size_t)b*H_ + h)*L_ + lg)*S_;
        float* prirow = out + OFF_PRI + (((size_t)b*H_ + h)*L_ + lg)*S_;
        #pragma unroll
        for (int jj = 0; jj < 16; ++jj) {
            int s = (jj >> 3)*SC + (jj & 7)*32 + lane;
            float p = sSer[r*SST + s] * rs[i];
            sSer[r*SST + s] = p;
            serrow[s] = p;
            float d = (float)(lg - s);
            prirow[s] = pc0[i] * __expf(pc1[i] * (d * d));
        }
    }

    // ---- PV: out[32x64] = series[32x512] @ V[512x64] ----
    // Warp wid owns e-range [wid*8, wid*8+8). lane = rg*4+ep:
    // rg in 0..7 selects row group, ep in 0..3 selects e-pair.
    const int rg = lane >> 2;
    const int ep = lane & 3;
    float2 pacc[4];
    #pragma unroll
    for (int i = 0; i < 4; ++i) pacc[i] = make_float2(0.f, 0.f);

    for (int ch = 0; ch < NCH; ++ch) {
        __syncthreads();   // also guards sSer finalize before cross-warp reads
        #pragma unroll 8
        for (int t = tid; t < SC*32; t += NT) {
            int r = t >> 5, c2 = t & 31;
            *(float2*)&sKV[r*KST + c2*2] =
                *(const float2*)&vb[(size_t)(ch*SC + r)*(H_*E_) + c2*2];
        }
        __syncthreads();

        #pragma unroll 2
        for (int k2 = 0; k2 < SC/2; ++k2) {
            int kk0 = ch*SC + k2*2;
            float2 a2[4];
            #pragma unroll
            for (int i = 0; i < 4; ++i)   // rows i*8+rg: conflict-free (SST%32==2)
                a2[i] = *(float2*)&sSer[(size_t)(i*8 + rg)*SST + kk0];
            float2 b0 = *(float2*)&sKV[(k2*2    )*KST + wid*8 + ep*2];
            float2 b1 = *(float2*)&sKV[(k2*2 + 1)*KST + wid*8 + ep*2];
            #pragma unroll
            for (int i = 0; i < 4; ++i) {
                pacc[i] = ffma2(make_float2(a2[i].x, a2[i].x), b0, pacc[i]);
                pacc[i] = ffma2(make_float2(a2[i].y, a2[i].y), b1, pacc[i]);
            }
        }
    }

    // ---- Write V output [B,L,H,E] ----
    float* vout = out + (((size_t)b*L_ + l0)*H_ + h)*E_;
    #pragma unroll
    for (int i = 0; i < 4; ++i) {
        int r = i*8 + rg;
        *(float2*)&vout[(size_t)r*(H_*E_) + wid*8 + ep*2] = pacc[i];
    }
}

extern "C" void kernel_launch(void* const* d_in, const int* in_sizes, int n_in,
                              void* d_out, int out_size)
{
    const float* q  = (const float*)d_in[0];
    const float* k  = (const float*)d_in[1];
    const float* v  = (const float*)d_in[2];
    const float* sg = (const float*)d_in[3];
    float* out = (float*)d_out;

    cudaFuncSetAttribute(anomaly_attn_kernel,
                         cudaFuncAttributeMaxDynamicSharedMemorySize, SMEM_BYTES);

    dim3 grid(L_ / BL, H_, B_);   // (16, 8, 32)
    anomaly_attn_kernel<<<grid, NT, SMEM_BYTES>>>(q, k, v, sg, out);
}

// round 2
// speedup vs baseline: 1.4525x; 1.4525x over previous
#include <cuda_runtime.h>
#include <math.h>

// Problem constants
#define B_  32
#define L_  512
#define H_  8
#define E_  64
#define S_  512

// Tiling
#define BL  32          // query rows per CTA
#define SC  128         // key/value chunk rows held in smem
#define NCH 4           // S / SC
#define NT  256         // threads per CTA

// Padded smem strides (floats)
#define KST 66          // K/V tile row stride
#define SST 516         // series row stride: %32==4 -> conflict-free LDS.128 across 8 row-groups

#define SMEM_FLOATS (BL*E_ + SC*KST + BL*SST)
#define SMEM_BYTES  (SMEM_FLOATS * 4)   // 108,032 B -> 2 CTAs/SM

// Output layout: [ V (B,L,H,E) | series (B,H,L,S) | prior (B,H,L,S) ]
#define OFF_SER ((size_t)8388608)
#define OFF_PRI ((size_t)75497472)

// Packed f32x2 FMA (Blackwell): 2 fp32 FMAs per fma-pipe issue slot.
static __device__ __forceinline__ float2 ffma2(float2 a, float2 b, float2 c) {
    float2 d;
    asm("{\n\t"
        ".reg .b64 ra, rb, rc, rd;\n\t"
        "mov.b64 ra, {%2,%3};\n\t"
        "mov.b64 rb, {%4,%5};\n\t"
        "mov.b64 rc, {%6,%7};\n\t"
        "fma.rn.f32x2 rd, ra, rb, rc;\n\t"
        "mov.b64 {%0,%1}, rd;\n\t"
        "}"
        : "=f"(d.x), "=f"(d.y)
        : "f"(a.x), "f"(a.y), "f"(b.x), "f"(b.y), "f"(c.x), "f"(c.y));
    return d;
}

__global__ void __launch_bounds__(NT, 2)
anomaly_attn_kernel(const float* __restrict__ q,
                    const float* __restrict__ kg,
                    const float* __restrict__ vg,
                    const float* __restrict__ sg,
                    float* __restrict__ out)
{
    extern __shared__ float sm[];
    float* sQ   = sm;                 // [BL][E_]
    float* sKV  = sm + BL*E_;         // [SC][KST]
    float* sSer = sKV + SC*KST;       // [BL][SST]

    const int tid  = threadIdx.x;
    const int lane = tid & 31;
    const int wid  = tid >> 5;        // 0..7
    const int tile = blockIdx.x;      // 0..15
    const int h    = blockIdx.y;
    const int b    = blockIdx.z;
    const int l0   = tile * BL;

    const float* qb = q  + (((size_t)b*L_ + l0)*H_ + h)*E_;   // row stride H_*E_
    const float* kb = kg + ((size_t)b*L_*H_ + h)*E_;          // key row s: + s*H_*E_
    const float* vb = vg + ((size_t)b*L_*H_ + h)*E_;

    // ---- Load Q tile (32x64) ----
    #pragma unroll 4
    for (int t = tid; t < BL*32; t += NT) {
        int r = t >> 5, c2 = t & 31;
        *(float2*)&sQ[r*E_ + c2*2] =
            *(const float2*)&qb[(size_t)r*(H_*E_) + c2*2];
    }

    const float scale = 0.125f;   // 1/sqrt(64)
    float rs[4] = {0.f, 0.f, 0.f, 0.f};   // row sums of exp(logits)

    // ---- QK^T + exp, chunked over S ----
    for (int ch = 0; ch < NCH; ++ch) {
        __syncthreads();
        #pragma unroll 8
        for (int t = tid; t < SC*32; t += NT) {
            int r = t >> 5, c2 = t & 31;
            *(float2*)&sKV[r*KST + c2*2] =
                *(const float2*)&kb[(size_t)(ch*SC + r)*(H_*E_) + c2*2];
        }
        __syncthreads();

        float2 acc[4][4];
        #pragma unroll
        for (int i = 0; i < 4; ++i)
            #pragma unroll
            for (int j = 0; j < 4; ++j)
                acc[i][j] = make_float2(0.f, 0.f);

        #pragma unroll 4
        for (int e2 = 0; e2 < 32; ++e2) {
            float2 a[4], bb[4];
            #pragma unroll
            for (int i = 0; i < 4; ++i)       // broadcast loads
                a[i] = *(float2*)&sQ[(wid*4 + i)*E_ + e2*2];
            #pragma unroll
            for (int j = 0; j < 4; ++j)       // spread loads (2-phase min)
                bb[j] = *(float2*)&sKV[(j*32 + lane)*KST + e2*2];
            #pragma unroll
            for (int i = 0; i < 4; ++i)
                #pragma unroll
                for (int j = 0; j < 4; ++j)
                    acc[i][j] = ffma2(a[i], bb[j], acc[i][j]);
        }

        // exp (no max-shift: |logits| small, softmax shift-invariant)
        #pragma unroll
        for (int i = 0; i < 4; ++i) {
            int r = wid*4 + i;
            #pragma unroll
            for (int j = 0; j < 4; ++j) {
                int s = ch*SC + j*32 + lane;
                float p = __expf((acc[i][j].x + acc[i][j].y) * scale);
                sSer[r*SST + s] = p;
                rs[i] += p;
            }
        }
    }

    // ---- Row-sum reduce across the warp (warp owns rows wid*4..wid*4+3) ----
    #pragma unroll
    for (int i = 0; i < 4; ++i) {
        float x = rs[i];
        #pragma unroll
        for (int off = 16; off > 0; off >>= 1)
            x += __shfl_xor_sync(0xffffffffu, x, off);
        rs[i] = 1.0f / x;
    }

    // ---- Gaussian prior per-row constants ----
    // Reproduce reference's fp32 cancellation in (3^sig - 1):
    // accurate expm1, then quantize through fl32(1+u)-1.
    float pc0[4], pc1[4];
    #pragma unroll
    for (int i = 0; i < 4; ++i) {
        int lg = l0 + wid*4 + i;
        float sv = sg[((size_t)b*L_ + lg)*H_ + h];
        float s1 = 1.0f / (1.0f + __expf(-5.0f * sv)) + 1e-5f;
        float u  = expm1f(s1 * 1.0986122886681098f);       // 3^s1 - 1, accurate
        float t3 = __fadd_rn(__fadd_rn(1.0f, u), -1.0f);   // mimic fl32(3^s1) - 1
        pc0[i] = 0.3989422804014327f / t3;
        pc1[i] = -0.5f / (t3 * t3);
    }

    // ---- Normalize series, write series + prior to gmem, finalize sSer ----
    #pragma unroll
    for (int i = 0; i < 4; ++i) {
        int r  = wid*4 + i;
        int lg = l0 + r;
        float* serrow = out + OFF_SER + (((size_t)b*H_ + h)*L_ + lg)*S_;
        float* prirow = out + OFF_PRI + (((size_t)b*H_ + h)*L_ + lg)*S_;
        #pragma unroll
        for (int jj = 0; jj < 16; ++jj) {
            int s = jj*32 + lane;
            float p = sSer[r*SST + s] * rs[i];
            sSer[r*SST + s] = p;
            serrow[s] = p;
            float d = (float)(lg - s);
            prirow[s] = pc0[i] * __expf(pc1[i] * (d * d));
        }
    }

    // ---- PV: out[32x64] = series[32x512] @ V[512x64] ----
    // Warp wid owns e-range [wid*8, wid*8+8). lane = rg*4+ep:
    // rg in 0..7 selects row group, ep in 0..3 selects e-pair.
    const int rg = lane >> 2;
    const int ep = lane & 3;
    float2 pacc[4];
    #pragma unroll
    for (int i = 0; i < 4; ++i) pacc[i] = make_float2(0.f, 0.f);

    for (int ch = 0; ch < NCH; ++ch) {
        __syncthreads();   // also guards sSer finalize before cross-warp reads
        #pragma unroll 8
        for (int t = tid; t < SC*32; t += NT) {
            int r = t >> 5, c2 = t & 31;
            *(float2*)&sKV[r*KST + c2*2] =
                *(const float2*)&vb[(size_t)(ch*SC + r)*(H_*E_) + c2*2];
        }
        __syncthreads();

        // 4-k blocking: LDS.128 on series (conflict-free, SST%32==4),
        // 8 LDS per 16 ffma2.
        #pragma unroll 2
        for (int k4 = 0; k4 < SC/4; ++k4) {
            int k0 = ch*SC + k4*4;
            float4 a4[4];
            #pragma unroll
            for (int i = 0; i < 4; ++i)
                a4[i] = *(float4*)&sSer[(size_t)(i*8 + rg)*SST + k0];
            float2 bv[4];
            #pragma unroll
            for (int kk = 0; kk < 4; ++kk)
                bv[kk] = *(float2*)&sKV[(k4*4 + kk)*KST + wid*8 + ep*2];
            #pragma unroll
            for (int i = 0; i < 4; ++i) {
                pacc[i] = ffma2(make_float2(a4[i].x, a4[i].x), bv[0], pacc[i]);
                pacc[i] = ffma2(make_float2(a4[i].y, a4[i].y), bv[1], pacc[i]);
                pacc[i] = ffma2(make_float2(a4[i].z, a4[i].z), bv[2], pacc[i]);
                pacc[i] = ffma2(make_float2(a4[i].w, a4[i].w), bv[3], pacc[i]);
            }
        }
    }

    // ---- Write V output [B,L,H,E] ----
    float* vout = out + (((size_t)b*L_ + l0)*H_ + h)*E_;
    #pragma unroll
    for (int i = 0; i < 4; ++i) {
        int r = i*8 + rg;
        *(float2*)&vout[(size_t)r*(H_*E_) + wid*8 + ep*2] = pacc[i];
    }
}

extern "C" void kernel_launch(void* const* d_in, const int* in_sizes, int n_in,
                              void* d_out, int out_size)
{
    const float* q  = (const float*)d_in[0];
    const float* k  = (const float*)d_in[1];
    const float* v  = (const float*)d_in[2];
    const float* sg = (const float*)d_in[3];
    float* out = (float*)d_out;

    cudaFuncSetAttribute(anomaly_attn_kernel,
                         cudaFuncAttributeMaxDynamicSharedMemorySize, SMEM_BYTES);

    dim3 grid(L_ / BL, H_, B_);   // (16, 8, 32)
    anomaly_attn_kernel<<<grid, NT, SMEM_BYTES>>>(q, k, v, sg, out);
}